// round 4
// baseline (speedup 1.0000x reference)
#include <cuda_runtime.h>
#include <cuda_bf16.h>
#include <math.h>
#include <stdint.h>

#define NN    30000
#define NE    960000
#define ET    (NE + NN)
#define INDIM 4527
#define KPAD1 4544
#define HOGD  4464
#define HID   128
#define NG    64

// ---------------- scratch (device globals) ----------------------------------
__device__ float g_attn[NN * 2];
__device__ float g_h1[NN * 256];
__device__ float g_as1[NN * 2];
__device__ float g_ad1[NN * 2];
__device__ float g_agg1[NN * 256];
__device__ float g_h2[NN * HID];
__device__ float g_as2[NN];
__device__ float g_ad2[NN];
__device__ int   g_cntN[NN];
__device__ int   g_indptr[NN + 1];
__device__ int   g_cursor[NN];
__device__ int   g_srcs[ET];
__device__ float g_pool[NG * HID];
__device__ int   g_gcnt[NG];
__device__ __nv_bfloat16 g_W1Thi[256 * KPAD1];
__device__ __nv_bfloat16 g_W1Tlo[256 * KPAD1];
__device__ __nv_bfloat16 g_W2Thi[128 * 256];
__device__ __nv_bfloat16 g_W2Tlo[128 * 256];

// ---------------- helpers ---------------------------------------------------
__device__ __forceinline__ uint32_t smem_u32(const void* p) {
    uint32_t a;
    asm("{ .reg .u64 t; cvta.to.shared.u64 t, %1; cvt.u32.u64 %0, t; }"
        : "=r"(a) : "l"(p));
    return a;
}
__device__ __forceinline__ float warpSum(float v) {
#pragma unroll
    for (int o = 16; o; o >>= 1) v += __shfl_xor_sync(0xffffffffu, v, o);
    return v;
}
__device__ __forceinline__ float warpMax(float v) {
#pragma unroll
    for (int o = 16; o; o >>= 1) v = fmaxf(v, __shfl_xor_sync(0xffffffffu, v, o));
    return v;
}
__device__ __forceinline__ float lrelu(float v) { return v > 0.f ? v : 0.2f * v; }

__device__ __forceinline__ void mma16816(float c[4], const uint32_t a[4],
                                         uint32_t b0, uint32_t b1) {
    asm volatile(
        "mma.sync.aligned.m16n8k16.row.col.f32.bf16.bf16.f32 "
        "{%0,%1,%2,%3}, {%4,%5,%6,%7}, {%8,%9}, {%0,%1,%2,%3};"
        : "+f"(c[0]), "+f"(c[1]), "+f"(c[2]), "+f"(c[3])
        : "r"(a[0]), "r"(a[1]), "r"(a[2]), "r"(a[3]), "r"(b0), "r"(b1));
}
#define LDSM4(r0, r1, r2, r3, addr)                                           \
    asm volatile("ldmatrix.sync.aligned.m8n8.x4.shared.b16 {%0,%1,%2,%3}, [%4];" \
                 : "=r"(r0), "=r"(r1), "=r"(r2), "=r"(r3) : "r"(addr))
#define CP16(saddr, gaddr)                                                    \
    asm volatile("cp.async.cg.shared.global [%0], [%1], 16;"                  \
                 :: "r"(saddr), "l"(gaddr))
#define CP_COMMIT() asm volatile("cp.async.commit_group;" ::: "memory")
#define CP_WAIT0()  asm volatile("cp.async.wait_group 0;" ::: "memory")

__device__ __forceinline__ unsigned packbf(float v0, float v1, float& r0, float& r1) {
    __nv_bfloat16 h0 = __float2bfloat16(v0), h1 = __float2bfloat16(v1);
    r0 = v0 - __bfloat162float(h0);
    r1 = v1 - __bfloat162float(h1);
    unsigned short a = *(unsigned short*)&h0, b = *(unsigned short*)&h1;
    return (unsigned)a | ((unsigned)b << 16);
}
__device__ __forceinline__ unsigned packbf2(float v0, float v1) {
    __nv_bfloat16 h0 = __float2bfloat16(v0), h1 = __float2bfloat16(v1);
    unsigned short a = *(unsigned short*)&h0, b = *(unsigned short*)&h1;
    return (unsigned)a | ((unsigned)b << 16);
}

// ---------------- init -------------------------------------------------------
__global__ void k_init() {
    int i = blockIdx.x * blockDim.x + threadIdx.x;
    if (i < NN) g_cntN[i] = 1;
    if (i < NG * HID) g_pool[i] = 0.f;
    if (i < NG) g_gcnt[i] = 0;
}

// ---------------- attention gate --------------------------------------------
__global__ void k_attn(const float* __restrict__ x,
                       const float* __restrict__ aW,
                       const float* __restrict__ ab) {
    int n = blockIdx.x;
    int t = threadIdx.x;  // 128
    const float* xr = x + (size_t)n * INDIM;
    float p0 = 0.f, p1 = 0.f;
    for (int k = t; k < INDIM; k += 128) {
        float v = xr[k];
        p0 += v * aW[2 * k];
        p1 += v * aW[2 * k + 1];
    }
    p0 = warpSum(p0);
    p1 = warpSum(p1);
    __shared__ float s0[4], s1[4];
    if ((t & 31) == 0) { s0[t >> 5] = p0; s1[t >> 5] = p1; }
    __syncthreads();
    if (t == 0) {
        p0 = s0[0] + s0[1] + s0[2] + s0[3] + ab[0];
        p1 = s1[0] + s1[1] + s1[2] + s1[3] + ab[1];
        float m = fmaxf(p0, p1);
        float e0 = expf(p0 - m), e1 = expf(p1 - m);
        float inv = 1.f / (e0 + e1);
        g_attn[2 * n]     = e0 * inv;
        g_attn[2 * n + 1] = e1 * inv;
    }
}

// ---------------- weight split (+transpose to [n][k]) -----------------------
__global__ void k_split(const float* __restrict__ W1, const float* __restrict__ W2) {
    int i = blockIdx.x * blockDim.x + threadIdx.x;
    if (i < 256 * KPAD1) {
        int n = i / KPAD1, k = i % KPAD1;
        float v = (k < INDIM) ? W1[(size_t)k * 256 + n] : 0.f;
        __nv_bfloat16 h = __float2bfloat16(v);
        g_W1Thi[i] = h;
        g_W1Tlo[i] = __float2bfloat16(v - __bfloat162float(h));
    }
    if (i < 128 * 256) {
        int n = i / 256, k = i % 256;
        float v = W2[k * 128 + n];
        __nv_bfloat16 h = __float2bfloat16(v);
        g_W2Thi[i] = h;
        g_W2Tlo[i] = __float2bfloat16(v - __bfloat162float(h));
    }
}

// ---------------- mma.sync GEMM: C[M,NTOT] = split(A') @ split(BT)^T --------
// 512 threads, block tile 128x128, BK=32, warp tile 32x32 (4x4 warp grid).
// SMEM rows padded to 40 elems (80B): LDSM-friendly, conflict-free.
// hi/lo split kept as 3 accumulating MMAs per fragment.
#define PADK    40
#define TILEB   (128 * PADK * 2)                 // 10240 bytes per part
#define GSMEM_BYTES (1024 + 1024 + 8 * TILEB)    // align + gates + 2stage*2mat*2part

template <int K, int KPADT, int NTOT, bool GATED>
__global__ __launch_bounds__(512)
void k_gemm_mma(const float* __restrict__ A,
                const __nv_bfloat16* __restrict__ BThi,
                const __nv_bfloat16* __restrict__ BTlo,
                float* __restrict__ C) {
    constexpr int KT = KPADT / 32;
    extern __shared__ char smraw[];
    char* smb = (char*)(((uintptr_t)smraw + 1023) & ~(uintptr_t)1023);
    char* smgate = smb;                 // 128 * float2
    char* smA = smb + 1024;             // [stage][part] of TILEB
    char* smB = smb + 1024 + 4 * TILEB;
    const uint32_t sbA = smem_u32(smA);
    const uint32_t sbB = smem_u32(smB);

    const int tid = threadIdx.x;
    const int l = tid & 31, warp = tid >> 5;
    const int wm = warp >> 2, wn = warp & 3;     // 4x4 grid, 32x32 tiles
    const int bn = blockIdx.x * 128;
    const int bm = blockIdx.y * 128;

    if (GATED && tid < 128) {
        int grow = bm + tid;
        float2 g = (grow < NN) ? *(const float2*)&g_attn[2 * grow]
                               : make_float2(0.f, 0.f);
        *(float2*)(smgate + tid * 8) = g;
    }
    __syncthreads();

    float acc[2][4][4];
#pragma unroll
    for (int i = 0; i < 2; i++)
#pragma unroll
        for (int j = 0; j < 4; j++)
#pragma unroll
            for (int q = 0; q < 4; q++) acc[i][j][q] = 0.f;

    float areg[8];
    const int ar0 = tid >> 4;            // 0..31
    const int ac  = (tid & 15) * 2;      // 0..30

    auto ldgA = [&](int kt) {
        int gk = kt * 32 + ac;
        bool ok0 = gk < K, ok1 = gk + 1 < K;
#pragma unroll
        for (int i = 0; i < 4; i++) {
            int r = ar0 + 32 * i;
            int grow = bm + r;
            float v0 = 0.f, v1 = 0.f;
            if (grow < NN) {
                const float* arp = A + (size_t)grow * K;
                if (ok0) v0 = arp[gk];
                if (ok1) v1 = arp[gk + 1];
                if (GATED) {
                    float2 g = *(const float2*)(smgate + r * 8);
                    v0 *= (gk < HOGD) ? g.x : g.y;
                    v1 *= (gk + 1 < HOGD) ? g.x : g.y;
                }
            }
            areg[2 * i] = v0;
            areg[2 * i + 1] = v1;
        }
    };
    auto stsA = [&](int s) {
        char* ph = smA + (s * 2 + 0) * TILEB;
        char* pl = smA + (s * 2 + 1) * TILEB;
#pragma unroll
        for (int i = 0; i < 4; i++) {
            int r = ar0 + 32 * i;
            float r0, r1;
            unsigned hp = packbf(areg[2 * i], areg[2 * i + 1], r0, r1);
            unsigned lp = packbf2(r0, r1);
            int off = r * 80 + ac * 2;
            *(uint32_t*)(ph + off) = hp;
            *(uint32_t*)(pl + off) = lp;
        }
    };
    auto cpB = [&](int kt, int s) {
        int k0 = kt * 32;
        int row = tid >> 2, chunk = tid & 3;
        uint32_t so = (uint32_t)(row * 80 + chunk * 16);
        size_t go = (size_t)(bn + row) * KPADT + k0 + chunk * 8;
        CP16(sbB + (s * 2 + 0) * TILEB + so, (const char*)(BThi + go));
        CP16(sbB + (s * 2 + 1) * TILEB + so, (const char*)(BTlo + go));
    };

    // prologue
    cpB(0, 0);
    CP_COMMIT();
    ldgA(0);
    stsA(0);
    CP_WAIT0();
    __syncthreads();

    for (int kt = 0; kt < KT; kt++) {
        const int s = kt & 1;
        if (kt + 1 < KT) {
            cpB(kt + 1, s ^ 1);
            CP_COMMIT();
            ldgA(kt + 1);
        }
        // ---- MMA on stage s
        const uint32_t ah_base = sbA + (s * 2) * TILEB;
        const uint32_t al_base = ah_base + TILEB;
        const uint32_t bh_base = sbB + (s * 2) * TILEB;
        const uint32_t bl_base = bh_base + TILEB;
#pragma unroll
        for (int ks = 0; ks < 2; ks++) {
            const int k0 = ks * 16;
            // A fragments: rows wm*32 + mt*16 + (l&15), col k0 + (l>>4)*8
            uint32_t ah[2][4], al[2][4];
#pragma unroll
            for (int mt = 0; mt < 2; mt++) {
                uint32_t off = (uint32_t)((wm * 32 + mt * 16 + (l & 15)) * 80 +
                                          (k0 + (l >> 4) * 8) * 2);
                LDSM4(ah[mt][0], ah[mt][1], ah[mt][2], ah[mt][3], ah_base + off);
                LDSM4(al[mt][0], al[mt][1], al[mt][2], al[mt][3], al_base + off);
            }
            // B fragments: 2 x LDSM4 per part cover nt 0..3
            uint32_t bh[4][2], bl[4][2];
#pragma unroll
            for (int pr = 0; pr < 2; pr++) {
                int m = l >> 3;
                uint32_t off = (uint32_t)((wn * 32 + pr * 16 + (m >> 1) * 8 + (l & 7)) * 80 +
                                          (k0 + (m & 1) * 8) * 2);
                LDSM4(bh[pr * 2][0], bh[pr * 2][1], bh[pr * 2 + 1][0], bh[pr * 2 + 1][1],
                      bh_base + off);
                LDSM4(bl[pr * 2][0], bl[pr * 2][1], bl[pr * 2 + 1][0], bl[pr * 2 + 1][1],
                      bl_base + off);
            }
#pragma unroll
            for (int nt = 0; nt < 4; nt++)
#pragma unroll
                for (int mt = 0; mt < 2; mt++) {
                    mma16816(acc[mt][nt], ah[mt], bh[nt][0], bh[nt][1]);
                    mma16816(acc[mt][nt], ah[mt], bl[nt][0], bl[nt][1]);
                    mma16816(acc[mt][nt], al[mt], bh[nt][0], bh[nt][1]);
                }
        }
        if (kt + 1 < KT) stsA(s ^ 1);
        CP_WAIT0();
        __syncthreads();
    }

    // epilogue
    const int g = l >> 2, tq = l & 3;
#pragma unroll
    for (int mt = 0; mt < 2; mt++)
#pragma unroll
        for (int nt = 0; nt < 4; nt++) {
            int m0 = bm + wm * 32 + mt * 16 + g;
            int n = bn + wn * 32 + nt * 8 + 2 * tq;
            if (m0 < NN)
                *(float2*)&C[(size_t)m0 * NTOT + n] =
                    make_float2(acc[mt][nt][0], acc[mt][nt][1]);
            if (m0 + 8 < NN)
                *(float2*)&C[(size_t)(m0 + 8) * NTOT + n] =
                    make_float2(acc[mt][nt][2], acc[mt][nt][3]);
        }
}

// ---------------- alpha layer 1 ---------------------------------------------
__global__ void k_alpha1(const float* __restrict__ as1,
                         const float* __restrict__ ad1) {
    int w = (blockIdx.x * blockDim.x + threadIdx.x) >> 5;
    int l = threadIdx.x & 31;
    if (w >= NN) return;
    const float* hr = g_h1 + (size_t)w * 256;
    float ps0 = 0, pd0 = 0, ps1 = 0, pd1 = 0;
#pragma unroll
    for (int i = 0; i < 4; i++) {
        int d = l + i * 32;
        float v0 = hr[d], v1 = hr[128 + d];
        ps0 += v0 * as1[d];        pd0 += v0 * ad1[d];
        ps1 += v1 * as1[128 + d];  pd1 += v1 * ad1[128 + d];
    }
    ps0 = warpSum(ps0); pd0 = warpSum(pd0);
    ps1 = warpSum(ps1); pd1 = warpSum(pd1);
    if (l == 0) {
        g_as1[2 * w] = ps0; g_as1[2 * w + 1] = ps1;
        g_ad1[2 * w] = pd0; g_ad1[2 * w + 1] = pd1;
    }
}

// ---------------- CSR build --------------------------------------------------
__global__ void k_count(const int* __restrict__ ei) {
    int e = blockIdx.x * blockDim.x + threadIdx.x;
    if (e < NE) atomicAdd(&g_cntN[ei[NE + e]], 1);
}

__global__ void k_scan() {
    __shared__ int sh[1024];
    int t = threadIdx.x;
    const int CH = (NN + 1023) / 1024;
    int lo = t * CH, hi = min(lo + CH, NN);
    int s = 0;
    for (int i = lo; i < hi; i++) s += g_cntN[i];
    sh[t] = s;
    __syncthreads();
    for (int o = 1; o < 1024; o <<= 1) {
        int v = (t >= o) ? sh[t - o] : 0;
        __syncthreads();
        sh[t] += v;
        __syncthreads();
    }
    int run = (t == 0) ? 0 : sh[t - 1];
    for (int i = lo; i < hi; i++) { g_indptr[i] = run; run += g_cntN[i]; }
    if (t == 1023) g_indptr[NN] = sh[1023];
}

__global__ void k_self() {
    int i = blockIdx.x * blockDim.x + threadIdx.x;
    if (i < NN) { g_cursor[i] = 1; g_srcs[g_indptr[i]] = i; }
}

__global__ void k_scatter(const int* __restrict__ ei) {
    int e = blockIdx.x * blockDim.x + threadIdx.x;
    if (e < NE) {
        int s = ei[e], d = ei[NE + e];
        int pos = g_indptr[d] + atomicAdd(&g_cursor[d], 1);
        g_srcs[pos] = s;
    }
}

// ---------------- layer-1 aggregation ---------------------------------------
__global__ void k_agg1(const float* __restrict__ b1) {
    int w = (blockIdx.x * blockDim.x + threadIdx.x) >> 5;
    int l = threadIdx.x & 31;
    if (w >= NN) return;
    int beg = g_indptr[w], end = g_indptr[w + 1];
    float ad0 = g_ad1[2 * w], ad1 = g_ad1[2 * w + 1];

    float m0 = -1e30f, m1 = -1e30f;
    for (int j = beg + l; j < end; j += 32) {
        int s = g_srcs[j];
        m0 = fmaxf(m0, lrelu(g_as1[2 * s] + ad0));
        m1 = fmaxf(m1, lrelu(g_as1[2 * s + 1] + ad1));
    }
    m0 = warpMax(m0); m1 = warpMax(m1);

    float d0 = 0.f, d1 = 0.f;
    for (int j = beg + l; j < end; j += 32) {
        int s = g_srcs[j];
        d0 += expf(lrelu(g_as1[2 * s] + ad0) - m0);
        d1 += expf(lrelu(g_as1[2 * s + 1] + ad1) - m1);
    }
    d0 = warpSum(d0); d1 = warpSum(d1);
    float i0 = 1.f / (d0 + 1e-16f), i1 = 1.f / (d1 + 1e-16f);

    float acc[8] = {0, 0, 0, 0, 0, 0, 0, 0};
    for (int base = beg; base < end; base += 32) {
        int j = base + l;
        int s = 0; float w0 = 0.f, w1 = 0.f;
        if (j < end) {
            s = g_srcs[j];
            w0 = expf(lrelu(g_as1[2 * s] + ad0) - m0) * i0;
            w1 = expf(lrelu(g_as1[2 * s + 1] + ad1) - m1) * i1;
        }
        int cnt = min(32, end - base);
        for (int q = 0; q < cnt; q++) {
            int   sq  = __shfl_sync(0xffffffffu, s, q);
            float w0q = __shfl_sync(0xffffffffu, w0, q);
            float w1q = __shfl_sync(0xffffffffu, w1, q);
            const float* hp = g_h1 + (size_t)sq * 256 + l;
            acc[0] += w0q * hp[0];   acc[1] += w0q * hp[32];
            acc[2] += w0q * hp[64];  acc[3] += w0q * hp[96];
            acc[4] += w1q * hp[128]; acc[5] += w1q * hp[160];
            acc[6] += w1q * hp[192]; acc[7] += w1q * hp[224];
        }
    }
#pragma unroll
    for (int i = 0; i < 8; i++) {
        int d = l + i * 32;
        float v = acc[i] + b1[d];
        g_agg1[(size_t)w * 256 + d] = v > 0.f ? v : 0.f;
    }
}

// ---------------- alpha layer 2 ---------------------------------------------
__global__ void k_alpha2(const float* __restrict__ as2,
                         const float* __restrict__ ad2) {
    int w = (blockIdx.x * blockDim.x + threadIdx.x) >> 5;
    int l = threadIdx.x & 31;
    if (w >= NN) return;
    const float* hr = g_h2 + (size_t)w * 128;
    float ps = 0.f, pd = 0.f;
#pragma unroll
    for (int i = 0; i < 4; i++) {
        int d = l + i * 32;
        float v = hr[d];
        ps += v * as2[d];
        pd += v * ad2[d];
    }
    ps = warpSum(ps); pd = warpSum(pd);
    if (l == 0) { g_as2[w] = ps; g_ad2[w] = pd; }
}

// ---------------- layer-2 aggregation + pooling ------------------------------
__global__ void k_agg2(const float* __restrict__ b2,
                       const int* __restrict__ batch) {
    int w = (blockIdx.x * blockDim.x + threadIdx.x) >> 5;
    int l = threadIdx.x & 31;
    if (w >= NN) return;
    int beg = g_indptr[w], end = g_indptr[w + 1];
    float ad = g_ad2[w];

    float m = -1e30f;
    for (int j = beg + l; j < end; j += 32)
        m = fmaxf(m, lrelu(g_as2[g_srcs[j]] + ad));
    m = warpMax(m);

    float den = 0.f;
    for (int j = beg + l; j < end; j += 32)
        den += expf(lrelu(g_as2[g_srcs[j]] + ad) - m);
    den = warpSum(den);
    float inv = 1.f / (den + 1e-16f);

    float acc[4] = {0, 0, 0, 0};
    for (int base = beg; base < end; base += 32) {
        int j = base + l;
        int s = 0; float ww = 0.f;
        if (j < end) {
            s = g_srcs[j];
            ww = expf(lrelu(g_as2[s] + ad) - m) * inv;
        }
        int cnt = min(32, end - base);
        for (int q = 0; q < cnt; q++) {
            int   sq = __shfl_sync(0xffffffffu, s, q);
            float wq = __shfl_sync(0xffffffffu, ww, q);
            const float* hp = g_h2 + (size_t)sq * 128 + l;
            acc[0] += wq * hp[0];  acc[1] += wq * hp[32];
            acc[2] += wq * hp[64]; acc[3] += wq * hp[96];
        }
    }
    int b = batch[w];
#pragma unroll
    for (int i = 0; i < 4; i++) {
        int d = l + i * 32;
        float v = acc[i] + b2[d];
        v = v > 0.f ? v : 0.f;
        atomicAdd(&g_pool[b * 128 + d], v);
    }
    if (l == 0) atomicAdd(&g_gcnt[b], 1);
}

// ---------------- classifier head -------------------------------------------
__global__ void k_class(const float* __restrict__ Wc1, const float* __restrict__ bc1,
                        const float* __restrict__ Wc2, const float* __restrict__ bc2,
                        float* __restrict__ out) {
    int g = blockIdx.x, t = threadIdx.x;
    __shared__ float p[128];
    __shared__ float z[64];
    float c = fmaxf((float)g_gcnt[g], 1.f);
    p[t] = g_pool[g * 128 + t] / c;
    __syncthreads();
    if (t < 64) {
        float s = bc1[t];
        for (int i = 0; i < 128; i++) s += p[i] * Wc1[i * 64 + t];
        z[t] = s > 0.f ? s : 0.f;
    }
    __syncthreads();
    if (t < 4) {
        float s = bc2[t];
        for (int i = 0; i < 64; i++) s += z[i] * Wc2[i * 4 + t];
        out[g * 4 + t] = s;
    }
}

// ---------------- launch -----------------------------------------------------
extern "C" void kernel_launch(void* const* d_in, const int* in_sizes, int n_in,
                              void* d_out, int out_size) {
    const float* x      = (const float*)d_in[0];
    const int*   ei     = (const int*)d_in[1];
    const int*   batch  = (const int*)d_in[2];
    const float* attn_W = (const float*)d_in[3];
    const float* attn_b = (const float*)d_in[4];
    const float* W1     = (const float*)d_in[5];
    const float* as1    = (const float*)d_in[6];
    const float* ad1    = (const float*)d_in[7];
    const float* b1     = (const float*)d_in[8];
    const float* W2     = (const float*)d_in[9];
    const float* as2    = (const float*)d_in[10];
    const float* ad2    = (const float*)d_in[11];
    const float* b2     = (const float*)d_in[12];
    const float* Wc1    = (const float*)d_in[13];
    const float* bc1    = (const float*)d_in[14];
    const float* Wc2    = (const float*)d_in[15];
    const float* bc2    = (const float*)d_in[16];
    float* out = (float*)d_out;

    float* p_h1;   cudaGetSymbolAddress((void**)&p_h1, g_h1);
    float* p_agg1; cudaGetSymbolAddress((void**)&p_agg1, g_agg1);
    float* p_h2;   cudaGetSymbolAddress((void**)&p_h2, g_h2);
    __nv_bfloat16 *p_w1h, *p_w1l, *p_w2h, *p_w2l;
    cudaGetSymbolAddress((void**)&p_w1h, g_W1Thi);
    cudaGetSymbolAddress((void**)&p_w1l, g_W1Tlo);
    cudaGetSymbolAddress((void**)&p_w2h, g_W2Thi);
    cudaGetSymbolAddress((void**)&p_w2l, g_W2Tlo);

    cudaFuncSetAttribute(k_gemm_mma<INDIM, KPAD1, 256, true>,
                         cudaFuncAttributeMaxDynamicSharedMemorySize, GSMEM_BYTES);
    cudaFuncSetAttribute(k_gemm_mma<256, 256, 128, false>,
                         cudaFuncAttributeMaxDynamicSharedMemorySize, GSMEM_BYTES);

    const int MB = (NN + 127) / 128;  // 235

    k_init<<<(NN + 255) / 256, 256>>>();
    k_attn<<<NN, 128>>>(x, attn_W, attn_b);
    k_split<<<(256 * KPAD1 + 255) / 256, 256>>>(W1, W2);
    k_gemm_mma<INDIM, KPAD1, 256, true><<<dim3(2, MB), 512, GSMEM_BYTES>>>(x, p_w1h, p_w1l, p_h1);
    k_alpha1<<<(NN * 32 + 255) / 256, 256>>>(as1, ad1);
    k_count<<<(NE + 255) / 256, 256>>>(ei);
    k_scan<<<1, 1024>>>();
    k_self<<<(NN + 255) / 256, 256>>>();
    k_scatter<<<(NE + 255) / 256, 256>>>(ei);
    k_agg1<<<(NN * 32 + 255) / 256, 256>>>(b1);
    k_gemm_mma<256, 256, 128, false><<<dim3(1, MB), 512, GSMEM_BYTES>>>(p_agg1, p_w2h, p_w2l, p_h2);
    k_alpha2<<<(NN * 32 + 255) / 256, 256>>>(as2, ad2);
    k_agg2<<<(NN * 32 + 255) / 256, 256>>>(b2, batch);
    k_class<<<64, 128>>>(Wc1, bc1, Wc2, bc2, out);
}

// round 5
// speedup vs baseline: 1.9002x; 1.9002x over previous
#include <cuda_runtime.h>
#include <cuda_bf16.h>
#include <math.h>
#include <stdint.h>

#define NN    30000
#define NE    960000
#define ET    (NE + NN)
#define INDIM 4527
#define KPAD1 4544
#define HOGD  4464
#define HID   128
#define NG    64

// ---------------- scratch (device globals) ----------------------------------
__device__ float g_h1[NN * 256];
__device__ float g_as1[NN * 2];
__device__ float g_ad1[NN * 2];
__device__ float g_h2[NN * HID];
__device__ float g_as2[NN];
__device__ float g_ad2[NN];
__device__ int   g_cntN[NN];
__device__ int   g_indptr[NN + 1];
__device__ int   g_cursor[NN];
__device__ int   g_srcs[ET];
__device__ float g_pool[NG * HID];
__device__ int   g_gcnt[NG];
// pre-split bf16 operands (+128 row slack so OOB tile loads stay in-bounds)
__device__ __nv_bfloat16 g_xhi[(NN + 128) * KPAD1];
__device__ __nv_bfloat16 g_xlo[(NN + 128) * KPAD1];
__device__ __nv_bfloat16 g_a1hi[(NN + 128) * 256];
__device__ __nv_bfloat16 g_a1lo[(NN + 128) * 256];
__device__ __nv_bfloat16 g_W1Thi[256 * KPAD1];
__device__ __nv_bfloat16 g_W1Tlo[256 * KPAD1];
__device__ __nv_bfloat16 g_W2Thi[128 * 256];
__device__ __nv_bfloat16 g_W2Tlo[128 * 256];

// ---------------- helpers ---------------------------------------------------
__device__ __forceinline__ uint32_t smem_u32(const void* p) {
    uint32_t a;
    asm("{ .reg .u64 t; cvta.to.shared.u64 t, %1; cvt.u32.u64 %0, t; }"
        : "=r"(a) : "l"(p));
    return a;
}
__device__ __forceinline__ float warpSum(float v) {
#pragma unroll
    for (int o = 16; o; o >>= 1) v += __shfl_xor_sync(0xffffffffu, v, o);
    return v;
}
__device__ __forceinline__ float warpMax(float v) {
#pragma unroll
    for (int o = 16; o; o >>= 1) v = fmaxf(v, __shfl_xor_sync(0xffffffffu, v, o));
    return v;
}
__device__ __forceinline__ float lrelu(float v) { return v > 0.f ? v : 0.2f * v; }

__device__ __forceinline__ void mma16816(float c[4], const uint32_t a[4],
                                         uint32_t b0, uint32_t b1) {
    asm volatile(
        "mma.sync.aligned.m16n8k16.row.col.f32.bf16.bf16.f32 "
        "{%0,%1,%2,%3}, {%4,%5,%6,%7}, {%8,%9}, {%0,%1,%2,%3};"
        : "+f"(c[0]), "+f"(c[1]), "+f"(c[2]), "+f"(c[3])
        : "r"(a[0]), "r"(a[1]), "r"(a[2]), "r"(a[3]), "r"(b0), "r"(b1));
}
#define LDSM4(r0, r1, r2, r3, addr)                                           \
    asm volatile("ldmatrix.sync.aligned.m8n8.x4.shared.b16 {%0,%1,%2,%3}, [%4];" \
                 : "=r"(r0), "=r"(r1), "=r"(r2), "=r"(r3) : "r"(addr))
#define CP16(saddr, gaddr)                                                    \
    asm volatile("cp.async.cg.shared.global [%0], [%1], 16;"                  \
                 :: "r"(saddr), "l"(gaddr))
#define CP_COMMIT() asm volatile("cp.async.commit_group;" ::: "memory")
#define CP_WAIT0()  asm volatile("cp.async.wait_group 0;" ::: "memory")

__device__ __forceinline__ unsigned packsplit(float v0, float v1, float& r0, float& r1) {
    __nv_bfloat16 h0 = __float2bfloat16(v0), h1 = __float2bfloat16(v1);
    r0 = v0 - __bfloat162float(h0);
    r1 = v1 - __bfloat162float(h1);
    unsigned short a = *(unsigned short*)&h0, b = *(unsigned short*)&h1;
    return (unsigned)a | ((unsigned)b << 16);
}
__device__ __forceinline__ unsigned packlo(float v0, float v1) {
    __nv_bfloat16 h0 = __float2bfloat16(v0), h1 = __float2bfloat16(v1);
    unsigned short a = *(unsigned short*)&h0, b = *(unsigned short*)&h1;
    return (unsigned)a | ((unsigned)b << 16);
}

// ---------------- init -------------------------------------------------------
__global__ void k_init() {
    int i = blockIdx.x * blockDim.x + threadIdx.x;
    if (i < NN) g_cntN[i] = 1;
    if (i < NG * HID) g_pool[i] = 0.f;
    if (i < NG) g_gcnt[i] = 0;
}

// ---------------- attention gate + split gated x ----------------------------
__global__ void k_attn(const float* __restrict__ x,
                       const float* __restrict__ aW,
                       const float* __restrict__ ab) {
    int n = blockIdx.x;
    int t = threadIdx.x;  // 128
    const float* xr = x + (size_t)n * INDIM;
    float p0 = 0.f, p1 = 0.f;
    for (int k = t; k < INDIM; k += 128) {
        float v = xr[k];
        p0 += v * aW[2 * k];
        p1 += v * aW[2 * k + 1];
    }
    p0 = warpSum(p0);
    p1 = warpSum(p1);
    __shared__ float s0[4], s1[4];
    __shared__ float gg[2];
    if ((t & 31) == 0) { s0[t >> 5] = p0; s1[t >> 5] = p1; }
    __syncthreads();
    if (t == 0) {
        p0 = s0[0] + s0[1] + s0[2] + s0[3] + ab[0];
        p1 = s1[0] + s1[1] + s1[2] + s1[3] + ab[1];
        float m = fmaxf(p0, p1);
        float e0 = expf(p0 - m), e1 = expf(p1 - m);
        float inv = 1.f / (e0 + e1);
        gg[0] = e0 * inv;
        gg[1] = e1 * inv;
    }
    __syncthreads();
    float g0 = gg[0], g1 = gg[1];
    uint32_t* oh = (uint32_t*)(g_xhi + (size_t)n * KPAD1);
    uint32_t* ol = (uint32_t*)(g_xlo + (size_t)n * KPAD1);
    for (int p = t; p < KPAD1 / 2; p += 128) {
        int k = 2 * p;
        float v0 = 0.f, v1 = 0.f;
        if (k < INDIM)     v0 = xr[k] * ((k < HOGD) ? g0 : g1);
        if (k + 1 < INDIM) v1 = xr[k + 1] * ((k + 1 < HOGD) ? g0 : g1);
        float r0, r1;
        oh[p] = packsplit(v0, v1, r0, r1);
        ol[p] = packlo(r0, r1);
    }
}

// ---------------- weight split (+transpose to [n][k]) -----------------------
__global__ void k_split(const float* __restrict__ W1, const float* __restrict__ W2) {
    int i = blockIdx.x * blockDim.x + threadIdx.x;
    if (i < 256 * KPAD1) {
        int n = i / KPAD1, k = i % KPAD1;
        float v = (k < INDIM) ? W1[(size_t)k * 256 + n] : 0.f;
        __nv_bfloat16 h = __float2bfloat16(v);
        g_W1Thi[i] = h;
        g_W1Tlo[i] = __float2bfloat16(v - __bfloat162float(h));
    }
    if (i < 128 * 256) {
        int n = i / 256, k = i % 256;
        float v = W2[k * 128 + n];
        __nv_bfloat16 h = __float2bfloat16(v);
        g_W2Thi[i] = h;
        g_W2Tlo[i] = __float2bfloat16(v - __bfloat162float(h));
    }
}

// ---------------- split-bf16 tensor GEMM, all-cp.async mainloop -------------
// 256 threads, block 128x128, BK=32, warp tile 64x32 (2x4 warp grid).
// SMEM stage = 4 parts (Ahi,Alo,Bhi,Blo) of 128 rows x 80B = 40960B; 2 stages.
#define PARTB   10240
#define STAGEB  40960
#define GSMEM_BYTES (2 * STAGEB)

template <int KPADT, int NTOT>
__global__ __launch_bounds__(256, 2)
void k_gemm_cp(const __nv_bfloat16* __restrict__ Ahi,
               const __nv_bfloat16* __restrict__ Alo,
               const __nv_bfloat16* __restrict__ Bhi,
               const __nv_bfloat16* __restrict__ Blo,
               float* __restrict__ C) {
    constexpr int KT = KPADT / 32;
    extern __shared__ char sm[];
    const uint32_t sb = smem_u32(sm);
    const int tid = threadIdx.x;
    const int l = tid & 31, w = tid >> 5;
    const int wm = w >> 2, wn = w & 3;       // 2x4 grid, 64x32 warp tiles
    const int bn = blockIdx.x * 128;
    const int bm = blockIdx.y * 128;

    // cp.async mapping: thread -> row tid>>1, chunk pair (tid&1)*2
    const int crow = tid >> 1;
    const int cc = (tid & 1) * 2;
    const __nv_bfloat16* aHiP = Ahi + (size_t)(bm + crow) * KPADT + cc * 8;
    const __nv_bfloat16* aLoP = Alo + (size_t)(bm + crow) * KPADT + cc * 8;
    const __nv_bfloat16* bHiP = Bhi + (size_t)(bn + crow) * KPADT + cc * 8;
    const __nv_bfloat16* bLoP = Blo + (size_t)(bn + crow) * KPADT + cc * 8;
    const uint32_t cso = (uint32_t)(crow * 80 + cc * 16);

    float acc[4][4][4];
#pragma unroll
    for (int i = 0; i < 4; i++)
#pragma unroll
        for (int j = 0; j < 4; j++)
#pragma unroll
            for (int q = 0; q < 4; q++) acc[i][j][q] = 0.f;

    auto cpStage = [&](int kt, int s) {
        const int k0 = kt * 32;
        uint32_t d = sb + s * STAGEB + cso;
        CP16(d,                 (const char*)(aHiP + k0));
        CP16(d + 16,            (const char*)(aHiP + k0 + 8));
        CP16(d + PARTB,         (const char*)(aLoP + k0));
        CP16(d + PARTB + 16,    (const char*)(aLoP + k0 + 8));
        CP16(d + 2 * PARTB,      (const char*)(bHiP + k0));
        CP16(d + 2 * PARTB + 16, (const char*)(bHiP + k0 + 8));
        CP16(d + 3 * PARTB,      (const char*)(bLoP + k0));
        CP16(d + 3 * PARTB + 16, (const char*)(bLoP + k0 + 8));
    };

    // LDSM address components
    const uint32_t a_row = (uint32_t)(wm * 64 + (l & 15));
    const uint32_t a_col = (uint32_t)(((l >> 4) & 1) * 8);
    const uint32_t b_row = (uint32_t)(wn * 32 + ((l >> 4) & 1) * 8 + (l & 7));
    const uint32_t b_col = (uint32_t)(((l >> 3) & 1) * 8);

    cpStage(0, 0);
    CP_COMMIT();

    for (int kt = 0; kt < KT; kt++) {
        const int s = kt & 1;
        CP_WAIT0();
        __syncthreads();
        if (kt + 1 < KT) { cpStage(kt + 1, s ^ 1); CP_COMMIT(); }

        const uint32_t stb = sb + s * STAGEB;
#pragma unroll
        for (int ks = 0; ks < 2; ks++) {
            const uint32_t kb = (uint32_t)(ks * 16) * 2;
            uint32_t ah[4][4], al[4][4];
#pragma unroll
            for (int mt = 0; mt < 4; mt++) {
                uint32_t off = (a_row + mt * 16) * 80 + a_col * 2 + kb;
                LDSM4(ah[mt][0], ah[mt][1], ah[mt][2], ah[mt][3], stb + off);
                LDSM4(al[mt][0], al[mt][1], al[mt][2], al[mt][3],
                      stb + PARTB + off);
            }
            uint32_t bh[4][2], bl[4][2];
#pragma unroll
            for (int pr = 0; pr < 2; pr++) {
                uint32_t off = (b_row + pr * 16) * 80 + b_col * 2 + kb;
                LDSM4(bh[2 * pr][0], bh[2 * pr][1], bh[2 * pr + 1][0],
                      bh[2 * pr + 1][1], stb + 2 * PARTB + off);
                LDSM4(bl[2 * pr][0], bl[2 * pr][1], bl[2 * pr + 1][0],
                      bl[2 * pr + 1][1], stb + 3 * PARTB + off);
            }
#pragma unroll
            for (int nt = 0; nt < 4; nt++)
#pragma unroll
                for (int mt = 0; mt < 4; mt++) {
                    mma16816(acc[mt][nt], ah[mt], bh[nt][0], bh[nt][1]);
                    mma16816(acc[mt][nt], ah[mt], bl[nt][0], bl[nt][1]);
                    mma16816(acc[mt][nt], al[mt], bh[nt][0], bh[nt][1]);
                }
        }
    }

    // epilogue
    const int g = l >> 2, tq = l & 3;
#pragma unroll
    for (int mt = 0; mt < 4; mt++)
#pragma unroll
        for (int nt = 0; nt < 4; nt++) {
            int m0 = bm + wm * 64 + mt * 16 + g;
            int n = bn + wn * 32 + nt * 8 + 2 * tq;
            if (m0 < NN)
                *(float2*)&C[(size_t)m0 * NTOT + n] =
                    make_float2(acc[mt][nt][0], acc[mt][nt][1]);
            if (m0 + 8 < NN)
                *(float2*)&C[(size_t)(m0 + 8) * NTOT + n] =
                    make_float2(acc[mt][nt][2], acc[mt][nt][3]);
        }
}

// ---------------- alpha layer 1 ---------------------------------------------
__global__ void k_alpha1(const float* __restrict__ as1,
                         const float* __restrict__ ad1) {
    int w = (blockIdx.x * blockDim.x + threadIdx.x) >> 5;
    int l = threadIdx.x & 31;
    if (w >= NN) return;
    const float* hr = g_h1 + (size_t)w * 256;
    float ps0 = 0, pd0 = 0, ps1 = 0, pd1 = 0;
#pragma unroll
    for (int i = 0; i < 4; i++) {
        int d = l + i * 32;
        float v0 = hr[d], v1 = hr[128 + d];
        ps0 += v0 * as1[d];        pd0 += v0 * ad1[d];
        ps1 += v1 * as1[128 + d];  pd1 += v1 * ad1[128 + d];
    }
    ps0 = warpSum(ps0); pd0 = warpSum(pd0);
    ps1 = warpSum(ps1); pd1 = warpSum(pd1);
    if (l == 0) {
        g_as1[2 * w] = ps0; g_as1[2 * w + 1] = ps1;
        g_ad1[2 * w] = pd0; g_ad1[2 * w + 1] = pd1;
    }
}

// ---------------- CSR build --------------------------------------------------
__global__ void k_count(const int* __restrict__ ei) {
    int e = blockIdx.x * blockDim.x + threadIdx.x;
    if (e < NE) atomicAdd(&g_cntN[ei[NE + e]], 1);
}

__global__ void k_scan() {
    __shared__ int sh[1024];
    int t = threadIdx.x;
    const int CH = (NN + 1023) / 1024;
    int lo = t * CH, hi = min(lo + CH, NN);
    int s = 0;
    for (int i = lo; i < hi; i++) s += g_cntN[i];
    sh[t] = s;
    __syncthreads();
    for (int o = 1; o < 1024; o <<= 1) {
        int v = (t >= o) ? sh[t - o] : 0;
        __syncthreads();
        sh[t] += v;
        __syncthreads();
    }
    int run = (t == 0) ? 0 : sh[t - 1];
    for (int i = lo; i < hi; i++) { g_indptr[i] = run; run += g_cntN[i]; }
    if (t == 1023) g_indptr[NN] = sh[1023];
}

__global__ void k_self() {
    int i = blockIdx.x * blockDim.x + threadIdx.x;
    if (i < NN) { g_cursor[i] = 1; g_srcs[g_indptr[i]] = i; }
}

__global__ void k_scatter(const int* __restrict__ ei) {
    int e = blockIdx.x * blockDim.x + threadIdx.x;
    if (e < NE) {
        int s = ei[e], d = ei[NE + e];
        int pos = g_indptr[d] + atomicAdd(&g_cursor[d], 1);
        g_srcs[pos] = s;
    }
}

// ---------------- layer-1 aggregation (emits split bf16) --------------------
__global__ void k_agg1(const float* __restrict__ b1) {
    int w = (blockIdx.x * blockDim.x + threadIdx.x) >> 5;
    int l = threadIdx.x & 31;
    if (w >= NN) return;
    int beg = g_indptr[w], end = g_indptr[w + 1];
    float ad0 = g_ad1[2 * w], ad1 = g_ad1[2 * w + 1];

    float m0 = -1e30f, m1 = -1e30f;
    for (int j = beg + l; j < end; j += 32) {
        int s = g_srcs[j];
        m0 = fmaxf(m0, lrelu(g_as1[2 * s] + ad0));
        m1 = fmaxf(m1, lrelu(g_as1[2 * s + 1] + ad1));
    }
    m0 = warpMax(m0); m1 = warpMax(m1);

    float d0 = 0.f, d1 = 0.f;
    for (int j = beg + l; j < end; j += 32) {
        int s = g_srcs[j];
        d0 += expf(lrelu(g_as1[2 * s] + ad0) - m0);
        d1 += expf(lrelu(g_as1[2 * s + 1] + ad1) - m1);
    }
    d0 = warpSum(d0); d1 = warpSum(d1);
    float i0 = 1.f / (d0 + 1e-16f), i1 = 1.f / (d1 + 1e-16f);

    float acc[8] = {0, 0, 0, 0, 0, 0, 0, 0};
    for (int base = beg; base < end; base += 32) {
        int j = base + l;
        int s = 0; float w0 = 0.f, w1 = 0.f;
        if (j < end) {
            s = g_srcs[j];
            w0 = expf(lrelu(g_as1[2 * s] + ad0) - m0) * i0;
            w1 = expf(lrelu(g_as1[2 * s + 1] + ad1) - m1) * i1;
        }
        int cnt = min(32, end - base);
        for (int q = 0; q < cnt; q++) {
            int   sq  = __shfl_sync(0xffffffffu, s, q);
            float w0q = __shfl_sync(0xffffffffu, w0, q);
            float w1q = __shfl_sync(0xffffffffu, w1, q);
            const float* hp = g_h1 + (size_t)sq * 256 + l;
            acc[0] += w0q * hp[0];   acc[1] += w0q * hp[32];
            acc[2] += w0q * hp[64];  acc[3] += w0q * hp[96];
            acc[4] += w1q * hp[128]; acc[5] += w1q * hp[160];
            acc[6] += w1q * hp[192]; acc[7] += w1q * hp[224];
        }
    }
#pragma unroll
    for (int i = 0; i < 8; i++) {
        int d = l + i * 32;
        float v = acc[i] + b1[d];
        v = v > 0.f ? v : 0.f;
        __nv_bfloat16 h = __float2bfloat16(v);
        g_a1hi[(size_t)w * 256 + d] = h;
        g_a1lo[(size_t)w * 256 + d] = __float2bfloat16(v - __bfloat162float(h));
    }
}

// ---------------- alpha layer 2 ---------------------------------------------
__global__ void k_alpha2(const float* __restrict__ as2,
                         const float* __restrict__ ad2) {
    int w = (blockIdx.x * blockDim.x + threadIdx.x) >> 5;
    int l = threadIdx.x & 31;
    if (w >= NN) return;
    const float* hr = g_h2 + (size_t)w * 128;
    float ps = 0.f, pd = 0.f;
#pragma unroll
    for (int i = 0; i < 4; i++) {
        int d = l + i * 32;
        float v = hr[d];
        ps += v * as2[d];
        pd += v * ad2[d];
    }
    ps = warpSum(ps); pd = warpSum(pd);
    if (l == 0) { g_as2[w] = ps; g_ad2[w] = pd; }
}

// ---------------- layer-2 aggregation + pooling ------------------------------
__global__ void k_agg2(const float* __restrict__ b2,
                       const int* __restrict__ batch) {
    int w = (blockIdx.x * blockDim.x + threadIdx.x) >> 5;
    int l = threadIdx.x & 31;
    if (w >= NN) return;
    int beg = g_indptr[w], end = g_indptr[w + 1];
    float ad = g_ad2[w];

    float m = -1e30f;
    for (int j = beg + l; j < end; j += 32)
        m = fmaxf(m, lrelu(g_as2[g_srcs[j]] + ad));
    m = warpMax(m);

    float den = 0.f;
    for (int j = beg + l; j < end; j += 32)
        den += expf(lrelu(g_as2[g_srcs[j]] + ad) - m);
    den = warpSum(den);
    float inv = 1.f / (den + 1e-16f);

    float acc[4] = {0, 0, 0, 0};
    for (int base = beg; base < end; base += 32) {
        int j = base + l;
        int s = 0; float ww = 0.f;
        if (j < end) {
            s = g_srcs[j];
            ww = expf(lrelu(g_as2[s] + ad) - m) * inv;
        }
        int cnt = min(32, end - base);
        for (int q = 0; q < cnt; q++) {
            int   sq = __shfl_sync(0xffffffffu, s, q);
            float wq = __shfl_sync(0xffffffffu, ww, q);
            const float* hp = g_h2 + (size_t)sq * 128 + l;
            acc[0] += wq * hp[0];  acc[1] += wq * hp[32];
            acc[2] += wq * hp[64]; acc[3] += wq * hp[96];
        }
    }
    int b = batch[w];
#pragma unroll
    for (int i = 0; i < 4; i++) {
        int d = l + i * 32;
        float v = acc[i] + b2[d];
        v = v > 0.f ? v : 0.f;
        atomicAdd(&g_pool[b * 128 + d], v);
    }
    if (l == 0) atomicAdd(&g_gcnt[b], 1);
}

// ---------------- classifier head -------------------------------------------
__global__ void k_class(const float* __restrict__ Wc1, const float* __restrict__ bc1,
                        const float* __restrict__ Wc2, const float* __restrict__ bc2,
                        float* __restrict__ out) {
    int g = blockIdx.x, t = threadIdx.x;
    __shared__ float p[128];
    __shared__ float z[64];
    float c = fmaxf((float)g_gcnt[g], 1.f);
    p[t] = g_pool[g * 128 + t] / c;
    __syncthreads();
    if (t < 64) {
        float s = bc1[t];
        for (int i = 0; i < 128; i++) s += p[i] * Wc1[i * 64 + t];
        z[t] = s > 0.f ? s : 0.f;
    }
    __syncthreads();
    if (t < 4) {
        float s = bc2[t];
        for (int i = 0; i < 64; i++) s += z[i] * Wc2[i * 4 + t];
        out[g * 4 + t] = s;
    }
}

// ---------------- launch -----------------------------------------------------
extern "C" void kernel_launch(void* const* d_in, const int* in_sizes, int n_in,
                              void* d_out, int out_size) {
    const float* x      = (const float*)d_in[0];
    const int*   ei     = (const int*)d_in[1];
    const int*   batch  = (const int*)d_in[2];
    const float* attn_W = (const float*)d_in[3];
    const float* attn_b = (const float*)d_in[4];
    const float* W1     = (const float*)d_in[5];
    const float* as1    = (const float*)d_in[6];
    const float* ad1    = (const float*)d_in[7];
    const float* b1     = (const float*)d_in[8];
    const float* W2     = (const float*)d_in[9];
    const float* as2    = (const float*)d_in[10];
    const float* ad2    = (const float*)d_in[11];
    const float* b2     = (const float*)d_in[12];
    const float* Wc1    = (const float*)d_in[13];
    const float* bc1    = (const float*)d_in[14];
    const float* Wc2    = (const float*)d_in[15];
    const float* bc2    = (const float*)d_in[16];
    float* out = (float*)d_out;

    float* p_h1;   cudaGetSymbolAddress((void**)&p_h1, g_h1);
    float* p_h2;   cudaGetSymbolAddress((void**)&p_h2, g_h2);
    __nv_bfloat16 *p_xh, *p_xl, *p_a1h, *p_a1l, *p_w1h, *p_w1l, *p_w2h, *p_w2l;
    cudaGetSymbolAddress((void**)&p_xh, g_xhi);
    cudaGetSymbolAddress((void**)&p_xl, g_xlo);
    cudaGetSymbolAddress((void**)&p_a1h, g_a1hi);
    cudaGetSymbolAddress((void**)&p_a1l, g_a1lo);
    cudaGetSymbolAddress((void**)&p_w1h, g_W1Thi);
    cudaGetSymbolAddress((void**)&p_w1l, g_W1Tlo);
    cudaGetSymbolAddress((void**)&p_w2h, g_W2Thi);
    cudaGetSymbolAddress((void**)&p_w2l, g_W2Tlo);

    cudaFuncSetAttribute(k_gemm_cp<KPAD1, 256>,
                         cudaFuncAttributeMaxDynamicSharedMemorySize, GSMEM_BYTES);
    cudaFuncSetAttribute(k_gemm_cp<256, 128>,
                         cudaFuncAttributeMaxDynamicSharedMemorySize, GSMEM_BYTES);

    const int MB = (NN + 127) / 128;  // 235

    k_init<<<(NN + 255) / 256, 256>>>();
    k_attn<<<NN, 128>>>(x, attn_W, attn_b);
    k_split<<<(256 * KPAD1 + 255) / 256, 256>>>(W1, W2);
    k_gemm_cp<KPAD1, 256><<<dim3(2, MB), 256, GSMEM_BYTES>>>(p_xh, p_xl, p_w1h, p_w1l, p_h1);
    k_alpha1<<<(NN * 32 + 255) / 256, 256>>>(as1, ad1);
    k_count<<<(NE + 255) / 256, 256>>>(ei);
    k_scan<<<1, 1024>>>();
    k_self<<<(NN + 255) / 256, 256>>>();
    k_scatter<<<(NE + 255) / 256, 256>>>(ei);
    k_agg1<<<(NN * 32 + 255) / 256, 256>>>(b1);
    k_gemm_cp<256, 128><<<dim3(1, MB), 256, GSMEM_BYTES>>>(p_a1h, p_a1l, p_w2h, p_w2l, p_h2);
    k_alpha2<<<(NN * 32 + 255) / 256, 256>>>(as2, ad2);
    k_agg2<<<(NN * 32 + 255) / 256, 256>>>(b2, batch);
    k_class<<<64, 128>>>(Wc1, bc1, Wc2, bc2, out);
}

// round 6
// speedup vs baseline: 2.0427x; 1.0750x over previous
#include <cuda_runtime.h>
#include <cuda_bf16.h>
#include <math.h>
#include <stdint.h>

#define NN    30000
#define NE    960000
#define ET    (NE + NN)
#define INDIM 4527
#define KPAD1 4544
#define HOGD  4464
#define HID   128
#define NG    64

// ---------------- scratch (device globals) ----------------------------------
__device__ float g_h1[NN * 256];
__device__ float g_as1[NN * 2];
__device__ float g_ad1[NN * 2];
__device__ float g_h2[NN * HID];
__device__ float g_as2[NN];
__device__ float g_ad2[NN];
__device__ int   g_cntN[NN];
__device__ int   g_indptr[NN + 1];
__device__ int   g_cursor[NN];
__device__ int   g_srcs[ET];
__device__ float g_pool[NG * HID];
__device__ int   g_gcnt[NG];
// pre-split bf16 operands (+128 row slack so OOB tile loads stay in-bounds)
__device__ __nv_bfloat16 g_xhi[(NN + 128) * KPAD1];
__device__ __nv_bfloat16 g_xlo[(NN + 128) * KPAD1];
__device__ __nv_bfloat16 g_a1hi[(NN + 128) * 256];
__device__ __nv_bfloat16 g_a1lo[(NN + 128) * 256];
__device__ __nv_bfloat16 g_W1Thi[256 * KPAD1];
__device__ __nv_bfloat16 g_W1Tlo[256 * KPAD1];
__device__ __nv_bfloat16 g_W2Thi[128 * 256];
__device__ __nv_bfloat16 g_W2Tlo[128 * 256];

// ---------------- helpers ---------------------------------------------------
__device__ __forceinline__ uint32_t smem_u32(const void* p) {
    uint32_t a;
    asm("{ .reg .u64 t; cvta.to.shared.u64 t, %1; cvt.u32.u64 %0, t; }"
        : "=r"(a) : "l"(p));
    return a;
}
__device__ __forceinline__ float warpSum(float v) {
#pragma unroll
    for (int o = 16; o; o >>= 1) v += __shfl_xor_sync(0xffffffffu, v, o);
    return v;
}
__device__ __forceinline__ float warpMax(float v) {
#pragma unroll
    for (int o = 16; o; o >>= 1) v = fmaxf(v, __shfl_xor_sync(0xffffffffu, v, o));
    return v;
}
__device__ __forceinline__ float lrelu(float v) { return v > 0.f ? v : 0.2f * v; }

__device__ __forceinline__ void mma16816(float c[4], const uint32_t a[4],
                                         uint32_t b0, uint32_t b1) {
    asm volatile(
        "mma.sync.aligned.m16n8k16.row.col.f32.bf16.bf16.f32 "
        "{%0,%1,%2,%3}, {%4,%5,%6,%7}, {%8,%9}, {%0,%1,%2,%3};"
        : "+f"(c[0]), "+f"(c[1]), "+f"(c[2]), "+f"(c[3])
        : "r"(a[0]), "r"(a[1]), "r"(a[2]), "r"(a[3]), "r"(b0), "r"(b1));
}
#define LDSM4(r0, r1, r2, r3, addr)                                           \
    asm volatile("ldmatrix.sync.aligned.m8n8.x4.shared.b16 {%0,%1,%2,%3}, [%4];" \
                 : "=r"(r0), "=r"(r1), "=r"(r2), "=r"(r3) : "r"(addr))
#define CP16(saddr, gaddr)                                                    \
    asm volatile("cp.async.cg.shared.global [%0], [%1], 16;"                  \
                 :: "r"(saddr), "l"(gaddr))
#define CP_COMMIT() asm volatile("cp.async.commit_group;" ::: "memory")
#define CP_WAIT1()  asm volatile("cp.async.wait_group 1;" ::: "memory")

__device__ __forceinline__ unsigned packsplit(float v0, float v1, float& r0, float& r1) {
    __nv_bfloat16 h0 = __float2bfloat16(v0), h1 = __float2bfloat16(v1);
    r0 = v0 - __bfloat162float(h0);
    r1 = v1 - __bfloat162float(h1);
    unsigned short a = *(unsigned short*)&h0, b = *(unsigned short*)&h1;
    return (unsigned)a | ((unsigned)b << 16);
}
__device__ __forceinline__ unsigned packlo(float v0, float v1) {
    __nv_bfloat16 h0 = __float2bfloat16(v0), h1 = __float2bfloat16(v1);
    unsigned short a = *(unsigned short*)&h0, b = *(unsigned short*)&h1;
    return (unsigned)a | ((unsigned)b << 16);
}

// ---------------- init -------------------------------------------------------
__global__ void k_init() {
    int i = blockIdx.x * blockDim.x + threadIdx.x;
    if (i < NN) g_cntN[i] = 1;
    if (i < NG * HID) g_pool[i] = 0.f;
    if (i < NG) g_gcnt[i] = 0;
}

// ---------------- attention gate + split gated x ----------------------------
__global__ void k_attn(const float* __restrict__ x,
                       const float* __restrict__ aW,
                       const float* __restrict__ ab) {
    int n = blockIdx.x;
    int t = threadIdx.x;  // 128
    const float* xr = x + (size_t)n * INDIM;
    float p0 = 0.f, p1 = 0.f;
    for (int k = t; k < INDIM; k += 128) {
        float v = xr[k];
        p0 += v * aW[2 * k];
        p1 += v * aW[2 * k + 1];
    }
    p0 = warpSum(p0);
    p1 = warpSum(p1);
    __shared__ float s0[4], s1[4];
    __shared__ float gg[2];
    if ((t & 31) == 0) { s0[t >> 5] = p0; s1[t >> 5] = p1; }
    __syncthreads();
    if (t == 0) {
        p0 = s0[0] + s0[1] + s0[2] + s0[3] + ab[0];
        p1 = s1[0] + s1[1] + s1[2] + s1[3] + ab[1];
        float m = fmaxf(p0, p1);
        float e0 = expf(p0 - m), e1 = expf(p1 - m);
        float inv = 1.f / (e0 + e1);
        gg[0] = e0 * inv;
        gg[1] = e1 * inv;
    }
    __syncthreads();
    float g0 = gg[0], g1 = gg[1];
    uint32_t* oh = (uint32_t*)(g_xhi + (size_t)n * KPAD1);
    uint32_t* ol = (uint32_t*)(g_xlo + (size_t)n * KPAD1);
    for (int p = t; p < KPAD1 / 2; p += 128) {
        int k = 2 * p;
        float v0 = 0.f, v1 = 0.f;
        if (k < INDIM)     v0 = xr[k] * ((k < HOGD) ? g0 : g1);
        if (k + 1 < INDIM) v1 = xr[k + 1] * ((k + 1 < HOGD) ? g0 : g1);
        float r0, r1;
        oh[p] = packsplit(v0, v1, r0, r1);
        ol[p] = packlo(r0, r1);
    }
}

// ---------------- weight split (+transpose to [n][k]) -----------------------
__global__ void k_split(const float* __restrict__ W1, const float* __restrict__ W2) {
    int i = blockIdx.x * blockDim.x + threadIdx.x;
    if (i < 256 * KPAD1) {
        int n = i / KPAD1, k = i % KPAD1;
        float v = (k < INDIM) ? W1[(size_t)k * 256 + n] : 0.f;
        __nv_bfloat16 h = __float2bfloat16(v);
        g_W1Thi[i] = h;
        g_W1Tlo[i] = __float2bfloat16(v - __bfloat162float(h));
    }
    if (i < 128 * 256) {
        int n = i / 256, k = i % 256;
        float v = W2[k * 128 + n];
        __nv_bfloat16 h = __float2bfloat16(v);
        g_W2Thi[i] = h;
        g_W2Tlo[i] = __float2bfloat16(v - __bfloat162float(h));
    }
}

// ---------------- split-bf16 tensor GEMM, 3-stage swizzled pipeline ---------
// 256 threads, block 128x128, BK=32, warp tile 64x32 (2x4 warp grid).
// Part = 128 rows x 64B, chunk-swizzled: c' = c ^ ((row>>1)&3).
// Stage = Ahi|Alo|Bhi|Blo = 32KB. 3 stages = 96KB -> 2 CTAs/SM.
#define PARTB   8192
#define STAGEB  (4 * PARTB)
#define GSMEM_BYTES (3 * STAGEB + 1024)

template <int KPADT, int NTOT>
__global__ __launch_bounds__(256, 2)
void k_gemm_cp(const __nv_bfloat16* __restrict__ Ahi,
               const __nv_bfloat16* __restrict__ Alo,
               const __nv_bfloat16* __restrict__ Bhi,
               const __nv_bfloat16* __restrict__ Blo,
               float* __restrict__ C) {
    constexpr int KT = KPADT / 32;
    extern __shared__ char smraw[];
    char* smb = (char*)(((uintptr_t)smraw + 1023) & ~(uintptr_t)1023);
    const uint32_t sb = smem_u32(smb);
    const int tid = threadIdx.x;
    const int l = tid & 31, w = tid >> 5;
    const int wm = w >> 2, wn = w & 3;       // 2x4 grid, 64x32 warp tiles
    const int bn = blockIdx.x * 128;
    const int bm = blockIdx.y * 128;

    // cp.async mapping: thread -> row tid>>1, chunk pair (tid&1)*2
    const int crow = tid >> 1;
    const int cp0 = (tid & 1) * 2;
    const int csw = (crow >> 1) & 3;
    const uint32_t cs0 = (uint32_t)(crow * 64 + ((cp0 ^ csw) * 16));
    const uint32_t cs1 = (uint32_t)(crow * 64 + (((cp0 + 1) ^ csw) * 16));
    const __nv_bfloat16* aHiP = Ahi + (size_t)(bm + crow) * KPADT + cp0 * 8;
    const __nv_bfloat16* aLoP = Alo + (size_t)(bm + crow) * KPADT + cp0 * 8;
    const __nv_bfloat16* bHiP = Bhi + (size_t)(bn + crow) * KPADT + cp0 * 8;
    const __nv_bfloat16* bLoP = Blo + (size_t)(bn + crow) * KPADT + cp0 * 8;

    float acc[4][4][4];
#pragma unroll
    for (int i = 0; i < 4; i++)
#pragma unroll
        for (int j = 0; j < 4; j++)
#pragma unroll
            for (int q = 0; q < 4; q++) acc[i][j][q] = 0.f;

    auto cpStage = [&](int kt, int s) {
        const int k0 = kt * 32;
        uint32_t d = sb + s * STAGEB;
        CP16(d + cs0,             (const char*)(aHiP + k0));
        CP16(d + cs1,             (const char*)(aHiP + k0 + 8));
        CP16(d + PARTB + cs0,     (const char*)(aLoP + k0));
        CP16(d + PARTB + cs1,     (const char*)(aLoP + k0 + 8));
        CP16(d + 2 * PARTB + cs0, (const char*)(bHiP + k0));
        CP16(d + 2 * PARTB + cs1, (const char*)(bHiP + k0 + 8));
        CP16(d + 3 * PARTB + cs0, (const char*)(bLoP + k0));
        CP16(d + 3 * PARTB + cs1, (const char*)(bLoP + k0 + 8));
    };

    // LDSM address components (row part; swizzle index is per-lane constant)
    const uint32_t a_roff = (uint32_t)((wm * 64 + (l & 15)) * 64);
    const int sA = ((l & 15) >> 1) & 3;
    const int aC = (l >> 4) & 1;                          // chunk half from lane
    const uint32_t b_rl = (uint32_t)(((l >> 4) & 1) * 8 + (l & 7));
    const uint32_t b_roff = (uint32_t)((wn * 32) * 64) + b_rl * 64;
    const int sB = (int)((b_rl >> 1) & 3);
    const int bC = (l >> 3) & 1;

    cpStage(0, 0);
    CP_COMMIT();
    cpStage(1, 1);
    CP_COMMIT();

    int s = 0;
    for (int kt = 0; kt < KT; kt++) {
        CP_WAIT1();
        __syncthreads();
        if (kt + 2 < KT) {
            int ns = s + 2; if (ns >= 3) ns -= 3;
            cpStage(kt + 2, ns);
        }
        CP_COMMIT();  // always commit (possibly empty) to keep group count aligned

        const uint32_t stb = sb + s * STAGEB;
#pragma unroll
        for (int ks = 0; ks < 2; ks++) {
            const uint32_t ca = (uint32_t)(((2 * ks + aC) ^ sA) * 16);
            const uint32_t cb = (uint32_t)(((2 * ks + bC) ^ sB) * 16);
            uint32_t ah[4][4], al[4][4];
#pragma unroll
            for (int mt = 0; mt < 4; mt++) {
                uint32_t off = a_roff + mt * 1024 + ca;
                LDSM4(ah[mt][0], ah[mt][1], ah[mt][2], ah[mt][3], stb + off);
                LDSM4(al[mt][0], al[mt][1], al[mt][2], al[mt][3],
                      stb + PARTB + off);
            }
            uint32_t bh[4][2], bl[4][2];
#pragma unroll
            for (int pr = 0; pr < 2; pr++) {
                uint32_t off = b_roff + pr * 1024 + cb;
                LDSM4(bh[2 * pr][0], bh[2 * pr][1], bh[2 * pr + 1][0],
                      bh[2 * pr + 1][1], stb + 2 * PARTB + off);
                LDSM4(bl[2 * pr][0], bl[2 * pr][1], bl[2 * pr + 1][0],
                      bl[2 * pr + 1][1], stb + 3 * PARTB + off);
            }
#pragma unroll
            for (int nt = 0; nt < 4; nt++)
#pragma unroll
                for (int mt = 0; mt < 4; mt++) {
                    mma16816(acc[mt][nt], ah[mt], bh[nt][0], bh[nt][1]);
                    mma16816(acc[mt][nt], ah[mt], bl[nt][0], bl[nt][1]);
                    mma16816(acc[mt][nt], al[mt], bh[nt][0], bh[nt][1]);
                }
        }
        if (++s == 3) s = 0;
    }

    // epilogue
    const int g = l >> 2, tq = l & 3;
#pragma unroll
    for (int mt = 0; mt < 4; mt++)
#pragma unroll
        for (int nt = 0; nt < 4; nt++) {
            int m0 = bm + wm * 64 + mt * 16 + g;
            int n = bn + wn * 32 + nt * 8 + 2 * tq;
            if (m0 < NN)
                *(float2*)&C[(size_t)m0 * NTOT + n] =
                    make_float2(acc[mt][nt][0], acc[mt][nt][1]);
            if (m0 + 8 < NN)
                *(float2*)&C[(size_t)(m0 + 8) * NTOT + n] =
                    make_float2(acc[mt][nt][2], acc[mt][nt][3]);
        }
}

// ---------------- alpha layer 1 ---------------------------------------------
__global__ void k_alpha1(const float* __restrict__ as1,
                         const float* __restrict__ ad1) {
    int w = (blockIdx.x * blockDim.x + threadIdx.x) >> 5;
    int l = threadIdx.x & 31;
    if (w >= NN) return;
    const float* hr = g_h1 + (size_t)w * 256;
    float ps0 = 0, pd0 = 0, ps1 = 0, pd1 = 0;
#pragma unroll
    for (int i = 0; i < 4; i++) {
        int d = l + i * 32;
        float v0 = hr[d], v1 = hr[128 + d];
        ps0 += v0 * as1[d];        pd0 += v0 * ad1[d];
        ps1 += v1 * as1[128 + d];  pd1 += v1 * ad1[128 + d];
    }
    ps0 = warpSum(ps0); pd0 = warpSum(pd0);
    ps1 = warpSum(ps1); pd1 = warpSum(pd1);
    if (l == 0) {
        g_as1[2 * w] = ps0; g_as1[2 * w + 1] = ps1;
        g_ad1[2 * w] = pd0; g_ad1[2 * w + 1] = pd1;
    }
}

// ---------------- CSR build --------------------------------------------------
__global__ void k_count(const int* __restrict__ ei) {
    int e = blockIdx.x * blockDim.x + threadIdx.x;
    if (e < NE) atomicAdd(&g_cntN[ei[NE + e]], 1);
}

__global__ void k_scan() {
    __shared__ int sh[1024];
    int t = threadIdx.x;
    const int CH = (NN + 1023) / 1024;
    int lo = t * CH, hi = min(lo + CH, NN);
    int s = 0;
    for (int i = lo; i < hi; i++) s += g_cntN[i];
    sh[t] = s;
    __syncthreads();
    for (int o = 1; o < 1024; o <<= 1) {
        int v = (t >= o) ? sh[t - o] : 0;
        __syncthreads();
        sh[t] += v;
        __syncthreads();
    }
    int run = (t == 0) ? 0 : sh[t - 1];
    for (int i = lo; i < hi; i++) { g_indptr[i] = run; run += g_cntN[i]; }
    if (t == 1023) g_indptr[NN] = sh[1023];
}

__global__ void k_self() {
    int i = blockIdx.x * blockDim.x + threadIdx.x;
    if (i < NN) { g_cursor[i] = 1; g_srcs[g_indptr[i]] = i; }
}

__global__ void k_scatter(const int* __restrict__ ei) {
    int e = blockIdx.x * blockDim.x + threadIdx.x;
    if (e < NE) {
        int s = ei[e], d = ei[NE + e];
        int pos = g_indptr[d] + atomicAdd(&g_cursor[d], 1);
        g_srcs[pos] = s;
    }
}

// ---------------- layer-1 aggregation (emits split bf16) --------------------
__global__ void k_agg1(const float* __restrict__ b1) {
    int w = (blockIdx.x * blockDim.x + threadIdx.x) >> 5;
    int l = threadIdx.x & 31;
    if (w >= NN) return;
    int beg = g_indptr[w], end = g_indptr[w + 1];
    float ad0 = g_ad1[2 * w], ad1 = g_ad1[2 * w + 1];

    float m0 = -1e30f, m1 = -1e30f;
    for (int j = beg + l; j < end; j += 32) {
        int s = g_srcs[j];
        m0 = fmaxf(m0, lrelu(g_as1[2 * s] + ad0));
        m1 = fmaxf(m1, lrelu(g_as1[2 * s + 1] + ad1));
    }
    m0 = warpMax(m0); m1 = warpMax(m1);

    float d0 = 0.f, d1 = 0.f;
    for (int j = beg + l; j < end; j += 32) {
        int s = g_srcs[j];
        d0 += expf(lrelu(g_as1[2 * s] + ad0) - m0);
        d1 += expf(lrelu(g_as1[2 * s + 1] + ad1) - m1);
    }
    d0 = warpSum(d0); d1 = warpSum(d1);
    float i0 = 1.f / (d0 + 1e-16f), i1 = 1.f / (d1 + 1e-16f);

    float acc[8] = {0, 0, 0, 0, 0, 0, 0, 0};
    for (int base = beg; base < end; base += 32) {
        int j = base + l;
        int s = 0; float w0 = 0.f, w1 = 0.f;
        if (j < end) {
            s = g_srcs[j];
            w0 = expf(lrelu(g_as1[2 * s] + ad0) - m0) * i0;
            w1 = expf(lrelu(g_as1[2 * s + 1] + ad1) - m1) * i1;
        }
        int cnt = min(32, end - base);
        for (int q = 0; q < cnt; q++) {
            int   sq  = __shfl_sync(0xffffffffu, s, q);
            float w0q = __shfl_sync(0xffffffffu, w0, q);
            float w1q = __shfl_sync(0xffffffffu, w1, q);
            const float* hp = g_h1 + (size_t)sq * 256 + l;
            acc[0] += w0q * hp[0];   acc[1] += w0q * hp[32];
            acc[2] += w0q * hp[64];  acc[3] += w0q * hp[96];
            acc[4] += w1q * hp[128]; acc[5] += w1q * hp[160];
            acc[6] += w1q * hp[192]; acc[7] += w1q * hp[224];
        }
    }
#pragma unroll
    for (int i = 0; i < 8; i++) {
        int d = l + i * 32;
        float v = acc[i] + b1[d];
        v = v > 0.f ? v : 0.f;
        __nv_bfloat16 h = __float2bfloat16(v);
        g_a1hi[(size_t)w * 256 + d] = h;
        g_a1lo[(size_t)w * 256 + d] = __float2bfloat16(v - __bfloat162float(h));
    }
}

// ---------------- alpha layer 2 ---------------------------------------------
__global__ void k_alpha2(const float* __restrict__ as2,
                         const float* __restrict__ ad2) {
    int w = (blockIdx.x * blockDim.x + threadIdx.x) >> 5;
    int l = threadIdx.x & 31;
    if (w >= NN) return;
    const float* hr = g_h2 + (size_t)w * 128;
    float ps = 0.f, pd = 0.f;
#pragma unroll
    for (int i = 0; i < 4; i++) {
        int d = l + i * 32;
        float v = hr[d];
        ps += v * as2[d];
        pd += v * ad2[d];
    }
    ps = warpSum(ps); pd = warpSum(pd);
    if (l == 0) { g_as2[w] = ps; g_ad2[w] = pd; }
}

// ---------------- layer-2 aggregation + pooling ------------------------------
__global__ void k_agg2(const float* __restrict__ b2,
                       const int* __restrict__ batch) {
    int w = (blockIdx.x * blockDim.x + threadIdx.x) >> 5;
    int l = threadIdx.x & 31;
    if (w >= NN) return;
    int beg = g_indptr[w], end = g_indptr[w + 1];
    float ad = g_ad2[w];

    float m = -1e30f;
    for (int j = beg + l; j < end; j += 32)
        m = fmaxf(m, lrelu(g_as2[g_srcs[j]] + ad));
    m = warpMax(m);

    float den = 0.f;
    for (int j = beg + l; j < end; j += 32)
        den += expf(lrelu(g_as2[g_srcs[j]] + ad) - m);
    den = warpSum(den);
    float inv = 1.f / (den + 1e-16f);

    float acc[4] = {0, 0, 0, 0};
    for (int base = beg; base < end; base += 32) {
        int j = base + l;
        int s = 0; float ww = 0.f;
        if (j < end) {
            s = g_srcs[j];
            ww = expf(lrelu(g_as2[s] + ad) - m) * inv;
        }
        int cnt = min(32, end - base);
        for (int q = 0; q < cnt; q++) {
            int   sq = __shfl_sync(0xffffffffu, s, q);
            float wq = __shfl_sync(0xffffffffu, ww, q);
            const float* hp = g_h2 + (size_t)sq * 128 + l;
            acc[0] += wq * hp[0];  acc[1] += wq * hp[32];
            acc[2] += wq * hp[64]; acc[3] += wq * hp[96];
        }
    }
    int b = batch[w];
#pragma unroll
    for (int i = 0; i < 4; i++) {
        int d = l + i * 32;
        float v = acc[i] + b2[d];
        v = v > 0.f ? v : 0.f;
        atomicAdd(&g_pool[b * 128 + d], v);
    }
    if (l == 0) atomicAdd(&g_gcnt[b], 1);
}

// ---------------- classifier head -------------------------------------------
__global__ void k_class(const float* __restrict__ Wc1, const float* __restrict__ bc1,
                        const float* __restrict__ Wc2, const float* __restrict__ bc2,
                        float* __restrict__ out) {
    int g = blockIdx.x, t = threadIdx.x;
    __shared__ float p[128];
    __shared__ float z[64];
    float c = fmaxf((float)g_gcnt[g], 1.f);
    p[t] = g_pool[g * 128 + t] / c;
    __syncthreads();
    if (t < 64) {
        float s = bc1[t];
        for (int i = 0; i < 128; i++) s += p[i] * Wc1[i * 64 + t];
        z[t] = s > 0.f ? s : 0.f;
    }
    __syncthreads();
    if (t < 4) {
        float s = bc2[t];
        for (int i = 0; i < 64; i++) s += z[i] * Wc2[i * 4 + t];
        out[g * 4 + t] = s;
    }
}

// ---------------- launch -----------------------------------------------------
extern "C" void kernel_launch(void* const* d_in, const int* in_sizes, int n_in,
                              void* d_out, int out_size) {
    const float* x      = (const float*)d_in[0];
    const int*   ei     = (const int*)d_in[1];
    const int*   batch  = (const int*)d_in[2];
    const float* attn_W = (const float*)d_in[3];
    const float* attn_b = (const float*)d_in[4];
    const float* W1     = (const float*)d_in[5];
    const float* as1    = (const float*)d_in[6];
    const float* ad1    = (const float*)d_in[7];
    const float* b1     = (const float*)d_in[8];
    const float* W2     = (const float*)d_in[9];
    const float* as2    = (const float*)d_in[10];
    const float* ad2    = (const float*)d_in[11];
    const float* b2     = (const float*)d_in[12];
    const float* Wc1    = (const float*)d_in[13];
    const float* bc1    = (const float*)d_in[14];
    const float* Wc2    = (const float*)d_in[15];
    const float* bc2    = (const float*)d_in[16];
    float* out = (float*)d_out;

    float* p_h1;   cudaGetSymbolAddress((void**)&p_h1, g_h1);
    float* p_h2;   cudaGetSymbolAddress((void**)&p_h2, g_h2);
    __nv_bfloat16 *p_xh, *p_xl, *p_a1h, *p_a1l, *p_w1h, *p_w1l, *p_w2h, *p_w2l;
    cudaGetSymbolAddress((void**)&p_xh, g_xhi);
    cudaGetSymbolAddress((void**)&p_xl, g_xlo);
    cudaGetSymbolAddress((void**)&p_a1h, g_a1hi);
    cudaGetSymbolAddress((void**)&p_a1l, g_a1lo);
    cudaGetSymbolAddress((void**)&p_w1h, g_W1Thi);
    cudaGetSymbolAddress((void**)&p_w1l, g_W1Tlo);
    cudaGetSymbolAddress((void**)&p_w2h, g_W2Thi);
    cudaGetSymbolAddress((void**)&p_w2l, g_W2Tlo);

    cudaFuncSetAttribute(k_gemm_cp<KPAD1, 256>,
                         cudaFuncAttributeMaxDynamicSharedMemorySize, GSMEM_BYTES);
    cudaFuncSetAttribute(k_gemm_cp<256, 128>,
                         cudaFuncAttributeMaxDynamicSharedMemorySize, GSMEM_BYTES);

    const int MB = (NN + 127) / 128;  // 235

    k_init<<<(NN + 255) / 256, 256>>>();
    k_attn<<<NN, 128>>>(x, attn_W, attn_b);
    k_split<<<(256 * KPAD1 + 255) / 256, 256>>>(W1, W2);
    k_gemm_cp<KPAD1, 256><<<dim3(2, MB), 256, GSMEM_BYTES>>>(p_xh, p_xl, p_w1h, p_w1l, p_h1);
    k_alpha1<<<(NN * 32 + 255) / 256, 256>>>(as1, ad1);
    k_count<<<(NE + 255) / 256, 256>>>(ei);
    k_scan<<<1, 1024>>>();
    k_self<<<(NN + 255) / 256, 256>>>();
    k_scatter<<<(NE + 255) / 256, 256>>>(ei);
    k_agg1<<<(NN * 32 + 255) / 256, 256>>>(b1);
    k_gemm_cp<256, 128><<<dim3(1, MB), 256, GSMEM_BYTES>>>(p_a1h, p_a1l, p_w2h, p_w2l, p_h2);
    k_alpha2<<<(NN * 32 + 255) / 256, 256>>>(as2, ad2);
    k_agg2<<<(NN * 32 + 255) / 256, 256>>>(b2, batch);
    k_class<<<64, 128>>>(Wc1, bc1, Wc2, bc2, out);
}